// round 13
// baseline (speedup 1.0000x reference)
#include <cuda_runtime.h>
#include <cuda_bf16.h>

#define NUM_SEG 32
#define C 256
#define C4 64   // float4 per row

// Scratch (allocation-free rule: __device__ globals).
// Invariants restored every launch (graph-replay safe, deterministic):
//   g_sum  : zero at entry (last reduce block consumer-resets after the MLP)
//   g_done : zero at entry (last reduce block writes 0 after detection)
__device__ float    g_sum[NUM_SEG * C];
__device__ int      g_lb[NUM_SEG + 1];    // segment lower bounds
__device__ float4   g_y4[NUM_SEG * C4];   // gates, float4-aligned
__device__ unsigned g_done;

// ---------------------------------------------------------------------------
// Kernel 1: segment sum + inline MLP epilogue.
// Streaming part: single-wave even partition at full occupancy (152 SMs * 8
// CTAs, 64 warps/SM). Each block owns a contiguous equal slice of rows;
// 128-row chunks with a branch-free __ldcs fast path when the whole chunk is
// one segment, per-row fallback at boundaries; atomic flush only on segment
// change. Blocks 0..32 also compute the lower_bound table concurrently
// (latency hidden under streaming).
// Epilogue: classic last-block pattern — every block does
// __threadfence(); __syncthreads(); thread0 atomicAdd(g_done). The block
// that observes old == gridDim-1 has a complete view of g_sum/g_lb and runs
// the full 32-segment MLP inline (~3-4us), writing the gates. This deletes
// the separate MLP kernel launch entirely.
// ---------------------------------------------------------------------------
#define RED_BLOCKS (152 * 8)
#define CHUNK 128

__device__ __forceinline__ void flush_acc(int seg, int c4, float4 a0, float4 a1) {
    float* dst = &g_sum[seg * C + c4 * 4];
    atomicAdd(dst + 0, a0.x + a1.x);
    atomicAdd(dst + 1, a0.y + a1.y);
    atomicAdd(dst + 2, a0.z + a1.z);
    atomicAdd(dst + 3, a0.w + a1.w);
}

__global__ void __launch_bounds__(256, 8)
se_reduce_kernel(const float4* __restrict__ feats,
                 const int*    __restrict__ idx,
                 const float*  __restrict__ W1,
                 const float*  __restrict__ b1,
                 const float*  __restrict__ W2,
                 const float*  __restrict__ b2,
                 int N) {
    const int t = threadIdx.x;

    // Segment-bound binary searches: run concurrently with streaming below.
    if (blockIdx.x <= NUM_SEG && t == 0) {
        int target = blockIdx.x;
        int lo = 0, hi = N;
        while (lo < hi) {
            int mid = (lo + hi) >> 1;
            if (__ldg(&idx[mid]) < target) lo = mid + 1; else hi = mid;
        }
        g_lb[target] = lo;
    }

    const int c4  = t & 63;   // channel float4 lane
    const int sub = t >> 6;   // 0..3

    long r0 = (long)blockIdx.x * N / gridDim.x;
    long r1 = (long)(blockIdx.x + 1) * N / gridDim.x;

    if (r0 < r1) {
        float4 a0 = make_float4(0.f, 0.f, 0.f, 0.f);
        float4 a1 = make_float4(0.f, 0.f, 0.f, 0.f);
        int cur = __ldg(&idx[r0]);

        long cs = r0;
        while (cs < r1) {
            long ce = cs + CHUNK;
            if (ce > r1) ce = r1;
            int s_last = __ldg(&idx[ce - 1]);

            if (s_last == cur) {
                // fast path: this thread's rows in the chunk are all seg cur.
                const float4* p = feats + (cs + sub) * C4 + c4;
                long r = cs + sub;
                for (; r + 4 < ce; r += 8) {
                    float4 v0 = __ldcs(p);
                    float4 v1 = __ldcs(p + 4 * C4);
                    a0.x += v0.x; a0.y += v0.y; a0.z += v0.z; a0.w += v0.w;
                    a1.x += v1.x; a1.y += v1.y; a1.z += v1.z; a1.w += v1.w;
                    p += 8 * C4;
                }
                for (; r < ce; r += 4) {
                    float4 v = __ldcs(p);
                    a0.x += v.x; a0.y += v.y; a0.z += v.z; a0.w += v.w;
                    p += 4 * C4;
                }
            } else {
                // boundary chunk: per-row segment tracking
                for (long r = cs + sub; r < ce; r += 4) {
                    int s = __ldg(&idx[r]);
                    float4 v = __ldcs(feats + r * C4 + c4);
                    if (s != cur) {
                        flush_acc(cur, c4, a0, a1);
                        a0 = v;
                        a1 = make_float4(0.f, 0.f, 0.f, 0.f);
                        cur = s;
                    } else {
                        a0.x += v.x; a0.y += v.y; a0.z += v.z; a0.w += v.w;
                    }
                }
            }
            cs = ce;
        }
        flush_acc(cur, c4, a0, a1);
    }

    // ---- last-block detection ----
    __shared__ unsigned s_islast;
    __threadfence();                       // order this thread's writes
    __syncthreads();                       // all threads of block fenced
    if (t == 0) {
        unsigned old = atomicAdd(&g_done, 1u);
        s_islast = (old == (unsigned)gridDim.x - 1u) ? 1u : 0u;
        if (s_islast) g_done = 0u;         // restore launch invariant
    }
    __syncthreads();

    // ---- inline MLP epilogue (exactly one block executes this) ----
    if (s_islast) {
        __shared__ float sp[C];
        __shared__ float sh[16];
        for (int s = 0; s < NUM_SEG; s++) {
            int cnt = __ldcg(&g_lb[s + 1]) - __ldcg(&g_lb[s]);
            float inv = 1.0f / fmaxf((float)cnt, 1.0f);
            sp[t] = __ldcg(&g_sum[s * C + t]) * inv;
            g_sum[s * C + t] = 0.0f;       // consumer reset
            __syncthreads();

            // h[g] = relu(dot(sp, W1[:,g]) + b1[g]); 16 threads per output
            {
                int g = t >> 4;
                int l = t & 15;
                float acc = 0.0f;
                #pragma unroll
                for (int k = l; k < C; k += 16) acc += sp[k] * W1[k * 16 + g];
                #pragma unroll
                for (int off = 8; off; off >>= 1)
                    acc += __shfl_down_sync(0xffffffffu, acc, off, 16);
                if (l == 0) sh[g] = fmaxf(acc + b1[g], 0.0f);
            }
            __syncthreads();

            // y[t] = sigmoid(dot(sh, W2[:,t]) + b2[t])
            float acc = b2[t];
            #pragma unroll
            for (int k = 0; k < 16; k++) acc += sh[k] * W2[k * C + t];
            ((float*)g_y4)[s * C + t] = 1.0f / (1.0f + __expf(-acc));
            __syncthreads();               // before reusing sp
        }
    }

    cudaTriggerProgrammaticLaunchCompletion();
}

// ---------------------------------------------------------------------------
// Kernel 2 (PDL dependent of reduce — single hop): out = feats * y[idx].
// R9-proven form: flat float4 grid-stride @ 2368 blocks, PLAIN loads/stores
// (298us @ 84.9% DRAM). Gate-independent prep (index math, idx load, first
// feats load) happens BEFORE the dependency sync, overlapping the reduce
// tail + inline MLP. Gates are complete when the reduce grid completes, so
// cudaGridDependencySynchronize alone is sufficient.
// ---------------------------------------------------------------------------
__global__ void __launch_bounds__(256, 8)
se_scale_kernel(const float4* __restrict__ feats,
                const int*    __restrict__ idx,
                float4*       __restrict__ out,
                long total4) {
    long stride = (long)gridDim.x * blockDim.x;
    long i0 = (long)blockIdx.x * blockDim.x + threadIdx.x;

    // Pre-sync prefetch of gate-independent data.
    int   row0 = (int)(i0 >> 6);
    float4 v0;
    int   s0 = 0;
    bool  have0 = (i0 < total4);
    if (have0) {
        s0 = __ldg(&idx[row0]);
        v0 = feats[i0];
    }

    cudaGridDependencySynchronize();

    if (have0) {
        int c4 = (int)(i0 & 63);
        float4 g = g_y4[s0 * C4 + c4];
        float4 o;
        o.x = v0.x * g.x; o.y = v0.y * g.y; o.z = v0.z * g.z; o.w = v0.w * g.w;
        out[i0] = o;
    }

    for (long i = i0 + stride; i < total4; i += stride) {
        int row = (int)(i >> 6);
        int c4  = (int)(i & 63);
        int s   = __ldg(&idx[row]);
        float4 v = feats[i];
        float4 g = g_y4[s * C4 + c4];
        float4 o;
        o.x = v.x * g.x; o.y = v.y * g.y; o.z = v.z * g.z; o.w = v.w * g.w;
        out[i] = o;
    }
}

// ---------------------------------------------------------------------------
extern "C" void kernel_launch(void* const* d_in, const int* in_sizes, int n_in,
                              void* d_out, int out_size) {
    const float* feats = (const float*)d_in[0];
    const int*   idx   = (const int*)  d_in[1];
    const float* W1    = (const float*)d_in[2];
    const float* b1    = (const float*)d_in[3];
    const float* W2    = (const float*)d_in[4];
    const float* b2    = (const float*)d_in[5];

    const int N = in_sizes[1];               // number of points
    const long total4 = (long)N * C4;

    // Kernel 1: reduce + inline MLP epilogue (plain launch).
    se_reduce_kernel<<<RED_BLOCKS, 256>>>((const float4*)feats, idx,
                                          W1, b1, W2, b2, N);

    // Kernel 2: programmatic dependent launch (spins up under reduce tail).
    cudaLaunchAttribute pdl_attr[1];
    pdl_attr[0].id = cudaLaunchAttributeProgrammaticStreamSerialization;
    pdl_attr[0].val.programmaticStreamSerializationAllowed = 1;

    cudaLaunchConfig_t cfg = {};
    cfg.gridDim  = dim3(2368, 1, 1);
    cfg.blockDim = dim3(256, 1, 1);
    cfg.dynamicSmemBytes = 0;
    cfg.stream = 0;
    cfg.attrs = pdl_attr;
    cfg.numAttrs = 1;
    cudaLaunchKernelEx(&cfg, se_scale_kernel,
                       (const float4*)feats, idx, (float4*)d_out, total4);
}

// round 14
// speedup vs baseline: 1.0988x; 1.0988x over previous
#include <cuda_runtime.h>
#include <cuda_bf16.h>

#define NUM_SEG 32
#define C 256
#define C4 64   // float4 per row

// Scratch (allocation-free rule: __device__ globals).
// Invariant: g_sum is ZERO at entry to every kernel_launch. Zero-initialized
// at module load; se_mlp_kernel re-zeroes it after consuming it, so the
// invariant is restored by every launch (deterministic, no zero pass).
__device__ float  g_sum[NUM_SEG * C];
__device__ int    g_lb[NUM_SEG + 1];    // segment lower bounds (written fresh each launch)
__device__ float4 g_y4[NUM_SEG * C4];   // gates, float4-aligned

// ---------------------------------------------------------------------------
// Kernel 1: segment sum, single-wave even partition at full occupancy
// (152 SMs * 8 CTAs, 64 warps/SM, 32 regs/thread). Each block owns a
// contiguous equal slice of rows. Walk in 128-row chunks: if
// idx[chunk_end-1] == cur (sorted => whole chunk one segment for this
// thread) take the branch-free streaming path; else per-row fallback.
// Atomic flush only on segment change. Blocks 0..32 also compute the
// lower_bound table concurrently (latency hidden under streaming).
// NOTE (R13 lesson): this kernel is at its 32-reg ceiling — do NOT add any
// code to it beyond the register-free binary searches.
// ---------------------------------------------------------------------------
#define RED_BLOCKS (152 * 8)
#define CHUNK 128

__device__ __forceinline__ void flush_acc(int seg, int c4, float4 a0, float4 a1) {
    float* dst = &g_sum[seg * C + c4 * 4];
    atomicAdd(dst + 0, a0.x + a1.x);
    atomicAdd(dst + 1, a0.y + a1.y);
    atomicAdd(dst + 2, a0.z + a1.z);
    atomicAdd(dst + 3, a0.w + a1.w);
}

__global__ void __launch_bounds__(256, 8)
se_reduce_kernel(const float4* __restrict__ feats,
                 const int*    __restrict__ idx,
                 int N) {
    // Segment-bound binary searches: run concurrently with streaming below.
    if (blockIdx.x <= NUM_SEG && threadIdx.x == 0) {
        int target = blockIdx.x;
        int lo = 0, hi = N;
        while (lo < hi) {
            int mid = (lo + hi) >> 1;
            if (__ldg(&idx[mid]) < target) lo = mid + 1; else hi = mid;
        }
        g_lb[target] = lo;
    }

    const int c4  = threadIdx.x & 63;   // channel float4 lane
    const int sub = threadIdx.x >> 6;   // 0..3

    long r0 = (long)blockIdx.x * N / gridDim.x;
    long r1 = (long)(blockIdx.x + 1) * N / gridDim.x;

    if (r0 < r1) {
        float4 a0 = make_float4(0.f, 0.f, 0.f, 0.f);
        float4 a1 = make_float4(0.f, 0.f, 0.f, 0.f);
        int cur = __ldg(&idx[r0]);

        long cs = r0;
        while (cs < r1) {
            long ce = cs + CHUNK;
            if (ce > r1) ce = r1;
            int s_last = __ldg(&idx[ce - 1]);

            if (s_last == cur) {
                // fast path: this thread's rows in the chunk are all seg cur.
                const float4* p = feats + (cs + sub) * C4 + c4;
                long r = cs + sub;
                for (; r + 4 < ce; r += 8) {
                    float4 v0 = __ldcs(p);
                    float4 v1 = __ldcs(p + 4 * C4);
                    a0.x += v0.x; a0.y += v0.y; a0.z += v0.z; a0.w += v0.w;
                    a1.x += v1.x; a1.y += v1.y; a1.z += v1.z; a1.w += v1.w;
                    p += 8 * C4;
                }
                for (; r < ce; r += 4) {
                    float4 v = __ldcs(p);
                    a0.x += v.x; a0.y += v.y; a0.z += v.z; a0.w += v.w;
                    p += 4 * C4;
                }
            } else {
                // boundary chunk: per-row segment tracking
                for (long r = cs + sub; r < ce; r += 4) {
                    int s = __ldg(&idx[r]);
                    float4 v = __ldcs(feats + r * C4 + c4);
                    if (s != cur) {
                        flush_acc(cur, c4, a0, a1);
                        a0 = v;
                        a1 = make_float4(0.f, 0.f, 0.f, 0.f);
                        cur = s;
                    } else {
                        a0.x += v.x; a0.y += v.y; a0.z += v.z; a0.w += v.w;
                    }
                }
            }
            cs = ce;
        }
        flush_acc(cur, c4, a0, a1);
    }

    // Writes issued: allow the dependent (MLP) grid to launch now.
    cudaTriggerProgrammaticLaunchCompletion();
}

// ---------------------------------------------------------------------------
// Kernel 2 (PDL dependent of reduce): one block per segment. Counts from
// g_lb, mean, 256->16 GEMM (16-thread groups + shuffle reduce), ReLU,
// 16->256 GEMM, sigmoid. Re-zeroes its g_sum slice (restores invariant).
// Triggers the scale kernel's programmatic launch at the end.
// ---------------------------------------------------------------------------
__global__ void se_mlp_kernel(const float* __restrict__ W1,
                              const float* __restrict__ b1,
                              const float* __restrict__ W2,
                              const float* __restrict__ b2) {
    const int s = blockIdx.x;
    const int t = threadIdx.x;
    __shared__ float sp[C];
    __shared__ float sh[16];

    // Wait until the reduce grid's writes (g_sum, g_lb) are visible.
    cudaGridDependencySynchronize();

    int cnt = __ldg(&g_lb[s + 1]) - __ldg(&g_lb[s]);
    float inv = 1.0f / fmaxf((float)cnt, 1.0f);
    sp[t] = g_sum[s * C + t] * inv;
    g_sum[s * C + t] = 0.0f;             // consumer reset
    __syncthreads();

    // h[g] = relu(dot(sp, W1[:,g]) + b1[g]); 16 threads per output g
    {
        int g = t >> 4;       // output 0..15
        int l = t & 15;       // lane within group
        float acc = 0.0f;
        #pragma unroll
        for (int k = l; k < C; k += 16) acc += sp[k] * W1[k * 16 + g];
        #pragma unroll
        for (int off = 8; off; off >>= 1)
            acc += __shfl_down_sync(0xffffffffu, acc, off, 16);
        if (l == 0) sh[g] = fmaxf(acc + b1[g], 0.0f);
    }
    __syncthreads();

    // y[t] = sigmoid(dot(sh, W2[:,t]) + b2[t])
    float acc = b2[t];
    #pragma unroll
    for (int k = 0; k < 16; k++) acc += sh[k] * W2[k * C + t];
    ((float*)g_y4)[s * C + t] = 1.0f / (1.0f + __expf(-acc));

    cudaTriggerProgrammaticLaunchCompletion();
}

// ---------------------------------------------------------------------------
// Kernel 3 (PDL dependent of mlp): out = feats * y[batch_idx]. Flat float4
// grid-stride @ 2368 blocks, PLAIN loads/stores (streaming hints, single-wave
// grids, reverse walks, and fusion all measurably hurt this RMW stream;
// this form is the proven 297-298us @ 85% DRAM ceiling). Gate-independent
// prep (index math, idx load, first feats load) happens BEFORE the
// dependency sync, overlapping the MLP.
// ---------------------------------------------------------------------------
__global__ void se_scale_kernel(const float4* __restrict__ feats,
                                const int*    __restrict__ idx,
                                float4*       __restrict__ out,
                                long total4) {
    long stride = (long)gridDim.x * blockDim.x;
    long i0 = (long)blockIdx.x * blockDim.x + threadIdx.x;

    // Pre-sync: start the first iteration's gate-independent loads.
    int   row0 = (int)(i0 >> 6);
    float4 v0;
    int   s0 = 0;
    bool  have0 = (i0 < total4);
    if (have0) {
        s0 = __ldg(&idx[row0]);
        v0 = feats[i0];
    }

    // Wait until the MLP grid's gate writes (g_y4) are visible.
    cudaGridDependencySynchronize();

    if (have0) {
        int c4 = (int)(i0 & 63);
        float4 g = g_y4[s0 * C4 + c4];
        float4 o;
        o.x = v0.x * g.x; o.y = v0.y * g.y; o.z = v0.z * g.z; o.w = v0.w * g.w;
        out[i0] = o;
    }

    for (long i = i0 + stride; i < total4; i += stride) {
        int row = (int)(i >> 6);
        int c4  = (int)(i & 63);
        int s   = __ldg(&idx[row]);
        float4 v = feats[i];
        float4 g = g_y4[s * C4 + c4];
        float4 o;
        o.x = v.x * g.x; o.y = v.y * g.y; o.z = v.z * g.z; o.w = v.w * g.w;
        out[i] = o;
    }
}

// ---------------------------------------------------------------------------
extern "C" void kernel_launch(void* const* d_in, const int* in_sizes, int n_in,
                              void* d_out, int out_size) {
    const float* feats = (const float*)d_in[0];
    const int*   idx   = (const int*)  d_in[1];
    const float* W1    = (const float*)d_in[2];
    const float* b1    = (const float*)d_in[3];
    const float* W2    = (const float*)d_in[4];
    const float* b2    = (const float*)d_in[5];

    const int N = in_sizes[1];               // number of points
    const long total4 = (long)N * C4;

    // Kernel 1: plain launch.
    se_reduce_kernel<<<RED_BLOCKS, 256>>>((const float4*)feats, idx, N);

    // Kernels 2 and 3: programmatic dependent launches (launch-latency
    // hiding; dependents spin up under the primary's tail, correctness via
    // cudaGridDependencySynchronize in the dependents).
    cudaLaunchAttribute pdl_attr[1];
    pdl_attr[0].id = cudaLaunchAttributeProgrammaticStreamSerialization;
    pdl_attr[0].val.programmaticStreamSerializationAllowed = 1;

    {
        cudaLaunchConfig_t cfg = {};
        cfg.gridDim  = dim3(NUM_SEG, 1, 1);
        cfg.blockDim = dim3(256, 1, 1);
        cfg.dynamicSmemBytes = 0;
        cfg.stream = 0;
        cfg.attrs = pdl_attr;
        cfg.numAttrs = 1;
        cudaLaunchKernelEx(&cfg, se_mlp_kernel, W1, b1, W2, b2);
    }
    {
        cudaLaunchConfig_t cfg = {};
        cfg.gridDim  = dim3(2368, 1, 1);
        cfg.blockDim = dim3(256, 1, 1);
        cfg.dynamicSmemBytes = 0;
        cfg.stream = 0;
        cfg.attrs = pdl_attr;
        cfg.numAttrs = 1;
        cudaLaunchKernelEx(&cfg, se_scale_kernel,
                           (const float4*)feats, idx, (float4*)d_out, total4);
    }
}